// round 3
// baseline (speedup 1.0000x reference)
#include <cuda_runtime.h>
#include <cuda_bf16.h>

#define GSZ   32
#define NCTRL 68
#define MLS_EPS 1e-8f

typedef unsigned long long u64;

// ---- packed f32x2 helpers (Blackwell sm_103a) ----
__device__ __forceinline__ u64 f2pack(float lo, float hi) {
    u64 r; asm("mov.b64 %0,{%1,%2};" : "=l"(r) : "f"(lo), "f"(hi)); return r;
}
__device__ __forceinline__ void f2unpack(u64 v, float& lo, float& hi) {
    asm("mov.b64 {%0,%1},%2;" : "=f"(lo), "=f"(hi) : "l"(v));
}
__device__ __forceinline__ u64 f2add(u64 a, u64 b) {
    u64 r; asm("add.rn.f32x2 %0,%1,%2;" : "=l"(r) : "l"(a), "l"(b)); return r;
}
__device__ __forceinline__ u64 f2mul(u64 a, u64 b) {
    u64 r; asm("mul.rn.f32x2 %0,%1,%2;" : "=l"(r) : "l"(a), "l"(b)); return r;
}
__device__ __forceinline__ u64 f2fma(u64 a, u64 b, u64 c) {
    u64 r; asm("fma.rn.f32x2 %0,%1,%2,%3;" : "=l"(r) : "l"(a), "l"(b), "l"(c)); return r;
}
// packed reciprocal in one asm region: lets ptxas colocate the register pairs
// so the unpack/pack MOVs can be elided.
__device__ __forceinline__ u64 f2rcp(u64 v) {
    u64 r;
    asm("{\n\t"
        ".reg .f32 lo, hi, rl, rh;\n\t"
        "mov.b64 {lo, hi}, %1;\n\t"
        "rcp.approx.f32 rl, lo;\n\t"
        "rcp.approx.f32 rh, hi;\n\t"
        "mov.b64 %0, {rl, rh};\n\t"
        "}" : "=l"(r) : "l"(v));
    return r;
}
__device__ __forceinline__ float frcp(float x) {
    float r; asm("rcp.approx.f32 %0,%1;" : "=f"(r) : "f"(x)); return r;
}

// Scalar epilogue: closed-form 2x2 solve from raw weighted moments.
__device__ __forceinline__ void mls_finish(
    float sw, float sx, float sy,
    float sxx, float sxy, float syy,
    float sqx, float sqy,
    float sdxqx, float sdyqx, float sdxqy, float sdyqy,
    float* __restrict__ ob, int pix)
{
    const float isw = frcp(sw);
    const float mx  = sx * isw,  my  = sy * isw;
    const float a11 = fmaf(sxx, isw, -(mx * mx));
    const float a12 = fmaf(sxy, isw, -(mx * my));
    const float a22 = fmaf(syy, isw, -(my * my));
    const float qsx = sqx * isw, qsy = sqy * isw;
    const float bxx = fmaf(sdxqx, isw, -(mx * qsx));
    const float bxy = fmaf(sdyqx, isw, -(my * qsx));
    const float byx = fmaf(sdxqy, isw, -(mx * qsy));
    const float byy = fmaf(sdyqy, isw, -(my * qsy));

    const float det  = fmaf(a11, a22, -(a12 * a12));
    const float idet = frcp(det);
    const float ux = -mx, uy = -my;
    const float rx = (ux * a22 - uy * a12) * idet;
    const float ry = (uy * a11 - ux * a12) * idet;

    float tx = fmaf(rx, bxx, fmaf(ry, bxy, qsx));
    float ty = fmaf(rx, byx, fmaf(ry, byy, qsy));

    // out-of-range pixels are ZEROED (not clipped)
    if (!(tx >= 0.f) || tx > (float)(GSZ - 1)) tx = 0.f;
    if (!(ty >= 0.f) || ty > (float)(GSZ - 1)) ty = 0.f;

    ob[pix]             = tx;   // channel 0 (x)
    ob[GSZ * GSZ + pix] = ty;   // channel 1 (y)
}

// 128 threads per CTA, each handles 2 pixels (pix, pix+128): same column,
// rows 4 apart. grid = (4, B): blockIdx.x selects an 8-row band.
// __launch_bounds__(128, 12) caps regs at 42 -> up to 48 warps/SM.
__global__ __launch_bounds__(128, 12)
void mls_warp_kernel(const float* __restrict__ sp,
                     const float* __restrict__ dp,
                     float* __restrict__ out)
{
    // Per control: 4 pre-duplicated f32x2 words: (kx,kx)(ky,ky)(qx,qx)(qy,qy)
    __shared__ __align__(16) u64 cs[NCTRL * 4];

    const int b    = blockIdx.y;
    const int band = blockIdx.x;     // 8-row band of the 32x32 grid
    const int tid  = threadIdx.x;

    if (tid < NCTRL) {
        const float* spb = sp + (size_t)b * (NCTRL * 2) + tid * 2;
        const float* dpb = dp + (size_t)b * (NCTRL * 2) + tid * 2;
        // coord swap + int16 truncation, exactly as the reference
        float kx = (float)(short)dpb[1];
        float ky = (float)(short)dpb[0];
        float qx = (float)(short)spb[1];
        float qy = (float)(short)spb[0];
        cs[tid * 4 + 0] = f2pack(kx, kx);
        cs[tid * 4 + 1] = f2pack(ky, ky);
        cs[tid * 4 + 2] = f2pack(qx, qx);
        cs[tid * 4 + 3] = f2pack(qy, qy);
    }
    __syncthreads();

    const int pixA = band * 256 + tid;         // pixB = pixA + 128
    const float vx  = (float)(tid & 31);
    const float vyA = (float)(band * 8 + (tid >> 5));
    const float vyB = vyA + 4.0f;

    const u64 nvx2 = f2pack(-vx, -vx);
    const u64 nvy2 = f2pack(-vyA, -vyB);
    const u64 eps2 = f2pack(MLS_EPS, MLS_EPS);

    u64 sw = 0, Sx = 0, Sy = 0;
    u64 Sxx = 0, Sxy = 0, Syy = 0;
    u64 Sqx = 0, Sqy = 0;
    u64 Sdxqx = 0, Sdyqx = 0, Sdxqy = 0, Sdyqy = 0;

    const ulonglong2* csv = (const ulonglong2*)cs;
#pragma unroll 2
    for (int c = 0; c < NCTRL; ++c) {
        ulonglong2 u0 = csv[c * 2 + 0];        // (kx2, ky2)

        u64 dx = f2add(u0.x, nvx2);
        u64 dy = f2add(u0.y, nvy2);
        u64 d2 = f2fma(dx, dx, f2fma(dy, dy, eps2));
        u64 w  = f2rcp(d2);

        u64 wdx = f2mul(w, dx);
        u64 wdy = f2mul(w, dy);

        sw  = f2add(sw, w);
        Sx  = f2add(Sx, wdx);
        Sy  = f2add(Sy, wdy);
        Sxx = f2fma(wdx, dx, Sxx);
        Sxy = f2fma(wdx, dy, Sxy);
        Syy = f2fma(wdy, dy, Syy);

        ulonglong2 u1 = csv[c * 2 + 1];        // (qx2, qy2)
        Sqx = f2fma(w, u1.x, Sqx);
        Sqy = f2fma(w, u1.y, Sqy);
        Sdxqx = f2fma(wdx, u1.x, Sdxqx);
        Sdyqx = f2fma(wdy, u1.x, Sdyqx);
        Sdxqy = f2fma(wdx, u1.y, Sdxqy);
        Sdyqy = f2fma(wdy, u1.y, Sdyqy);
    }

    float* ob = out + (size_t)b * (2 * GSZ * GSZ);

    float swl, swh, sxl, sxh, syl, syh;
    float sxxl, sxxh, sxyl, sxyh, syyl, syyh;
    float sqxl, sqxh, sqyl, sqyh;
    float s1l, s1h, s2l, s2h, s3l, s3h, s4l, s4h;
    f2unpack(sw, swl, swh);    f2unpack(Sx, sxl, sxh);    f2unpack(Sy, syl, syh);
    f2unpack(Sxx, sxxl, sxxh); f2unpack(Sxy, sxyl, sxyh); f2unpack(Syy, syyl, syyh);
    f2unpack(Sqx, sqxl, sqxh); f2unpack(Sqy, sqyl, sqyh);
    f2unpack(Sdxqx, s1l, s1h); f2unpack(Sdyqx, s2l, s2h);
    f2unpack(Sdxqy, s3l, s3h); f2unpack(Sdyqy, s4l, s4h);

    mls_finish(swl, sxl, syl, sxxl, sxyl, syyl, sqxl, sqyl, s1l, s2l, s3l, s4l, ob, pixA);
    mls_finish(swh, sxh, syh, sxxh, sxyh, syyh, sqxh, sqyh, s1h, s2h, s3h, s4h, ob, pixA + 128);
}

extern "C" void kernel_launch(void* const* d_in, const int* in_sizes, int n_in,
                              void* d_out, int out_size)
{
    const float* sp = (const float*)d_in[0];   // (B, 68, 2)
    const float* dp = (const float*)d_in[1];   // (B, 68, 2)
    float* out = (float*)d_out;                // (B, 2, 32, 32)

    int B = in_sizes[0] / (NCTRL * 2);         // 512 for this problem
    dim3 grid(4, B);
    mls_warp_kernel<<<grid, 128>>>(sp, dp, out);
}

// round 4
// speedup vs baseline: 1.0553x; 1.0553x over previous
#include <cuda_runtime.h>
#include <cuda_bf16.h>

#define GSZ   32
#define NCTRL 68
#define MLS_EPS 1e-8f

typedef unsigned long long u64;

// ---- packed f32x2 helpers (Blackwell sm_103a) ----
// All accumulating ops are IN-PLACE ("+l") so ptxas cannot insert result-
// marshaling MOVs: destination pair == addend pair by construction.
__device__ __forceinline__ u64 f2pack(float lo, float hi) {
    u64 r; asm("mov.b64 %0,{%1,%2};" : "=l"(r) : "f"(lo), "f"(hi)); return r;
}
__device__ __forceinline__ void f2unpack(u64 v, float& lo, float& hi) {
    asm("mov.b64 {%0,%1},%2;" : "=f"(lo), "=f"(hi) : "l"(v));
}
__device__ __forceinline__ u64 f2add(u64 a, u64 b) {
    u64 r; asm("add.rn.f32x2 %0,%1,%2;" : "=l"(r) : "l"(a), "l"(b)); return r;
}
__device__ __forceinline__ u64 f2mul(u64 a, u64 b) {
    u64 r; asm("mul.rn.f32x2 %0,%1,%2;" : "=l"(r) : "l"(a), "l"(b)); return r;
}
__device__ __forceinline__ u64 f2fma(u64 a, u64 b, u64 c) {
    u64 r; asm("fma.rn.f32x2 %0,%1,%2,%3;" : "=l"(r) : "l"(a), "l"(b), "l"(c)); return r;
}
// acc += a  (in place)
__device__ __forceinline__ void f2acc_add(u64& acc, u64 a) {
    asm("add.rn.f32x2 %0,%0,%1;" : "+l"(acc) : "l"(a));
}
// acc += a*b  (in place)
__device__ __forceinline__ void f2acc_fma(u64& acc, u64 a, u64 b) {
    asm("fma.rn.f32x2 %0,%1,%2,%0;" : "+l"(acc) : "l"(a), "l"(b));
}
// v = rcp.approx(v) per lane, in place: same pair in/out, MOVs coalesce away.
__device__ __forceinline__ void f2rcp_ip(u64& v) {
    asm("{\n\t"
        ".reg .f32 lo, hi;\n\t"
        "mov.b64 {lo, hi}, %0;\n\t"
        "rcp.approx.f32 lo, lo;\n\t"
        "rcp.approx.f32 hi, hi;\n\t"
        "mov.b64 %0, {lo, hi};\n\t"
        "}" : "+l"(v));
}
__device__ __forceinline__ float frcp(float x) {
    float r; asm("rcp.approx.f32 %0,%1;" : "=f"(r) : "f"(x)); return r;
}

// Scalar epilogue: closed-form 2x2 solve from raw weighted moments.
//  m = Sigma w~ (pf - v)  ->  p* = v + m, u = v - p* = -m
__device__ __forceinline__ void mls_finish(
    float sw, float sx, float sy,
    float sxx, float sxy, float syy,
    float sqx, float sqy,
    float sdxqx, float sdyqx, float sdxqy, float sdyqy,
    float* __restrict__ ob, int pix)
{
    const float isw = frcp(sw);
    const float mx  = sx * isw,  my  = sy * isw;
    const float a11 = fmaf(sxx, isw, -(mx * mx));
    const float a12 = fmaf(sxy, isw, -(mx * my));
    const float a22 = fmaf(syy, isw, -(my * my));
    const float qsx = sqx * isw, qsy = sqy * isw;
    const float bxx = fmaf(sdxqx, isw, -(mx * qsx));
    const float bxy = fmaf(sdyqx, isw, -(my * qsx));
    const float byx = fmaf(sdxqy, isw, -(mx * qsy));
    const float byy = fmaf(sdyqy, isw, -(my * qsy));

    const float det  = fmaf(a11, a22, -(a12 * a12));
    const float idet = frcp(det);
    const float ux = -mx, uy = -my;
    const float rx = (ux * a22 - uy * a12) * idet;
    const float ry = (uy * a11 - ux * a12) * idet;

    float tx = fmaf(rx, bxx, fmaf(ry, bxy, qsx));
    float ty = fmaf(rx, byx, fmaf(ry, byy, qsy));

    // out-of-range pixels are ZEROED (not clipped)
    if (!(tx >= 0.f) || tx > (float)(GSZ - 1)) tx = 0.f;
    if (!(ty >= 0.f) || ty > (float)(GSZ - 1)) ty = 0.f;

    ob[pix]             = tx;   // channel 0 (x)
    ob[GSZ * GSZ + pix] = ty;   // channel 1 (y)
}

// 128 threads per CTA, each handles 2 pixels (pix, pix+128): same column,
// rows 4 apart. grid = (4, B): blockIdx.x selects an 8-row band.
__global__ __launch_bounds__(128)
void mls_warp_kernel(const float* __restrict__ sp,
                     const float* __restrict__ dp,
                     float* __restrict__ out)
{
    // Per control: 4 pre-duplicated f32x2 words: (kx,kx)(ky,ky)(qx,qx)(qy,qy)
    __shared__ __align__(16) u64 cs[NCTRL * 4];

    const int b    = blockIdx.y;
    const int band = blockIdx.x;     // 8-row band of the 32x32 grid
    const int tid  = threadIdx.x;

    if (tid < NCTRL) {
        const float* spb = sp + (size_t)b * (NCTRL * 2) + tid * 2;
        const float* dpb = dp + (size_t)b * (NCTRL * 2) + tid * 2;
        // coord swap + int16 truncation, exactly as the reference
        float kx = (float)(short)dpb[1];
        float ky = (float)(short)dpb[0];
        float qx = (float)(short)spb[1];
        float qy = (float)(short)spb[0];
        cs[tid * 4 + 0] = f2pack(kx, kx);
        cs[tid * 4 + 1] = f2pack(ky, ky);
        cs[tid * 4 + 2] = f2pack(qx, qx);
        cs[tid * 4 + 3] = f2pack(qy, qy);
    }
    __syncthreads();

    const int pixA = band * 256 + tid;         // pixB = pixA + 128
    const float vx  = (float)(tid & 31);
    const float vyA = (float)(band * 8 + (tid >> 5));
    const float vyB = vyA + 4.0f;

    const u64 nvx2 = f2pack(-vx, -vx);
    const u64 nvy2 = f2pack(-vyA, -vyB);
    const u64 eps2 = f2pack(MLS_EPS, MLS_EPS);

    u64 sw = 0, Sx = 0, Sy = 0;
    u64 Sxx = 0, Sxy = 0, Syy = 0;
    u64 Sqx = 0, Sqy = 0;
    u64 Sdxqx = 0, Sdyqx = 0, Sdxqy = 0, Sdyqy = 0;

    const ulonglong2* csv = (const ulonglong2*)cs;
#pragma unroll 4
    for (int c = 0; c < NCTRL; ++c) {
        ulonglong2 u0 = csv[c * 2 + 0];        // (kx2, ky2)
        ulonglong2 u1 = csv[c * 2 + 1];        // (qx2, qy2)

        u64 dx = f2add(u0.x, nvx2);
        u64 dy = f2add(u0.y, nvy2);
        u64 w  = f2fma(dx, dx, f2fma(dy, dy, eps2));
        f2rcp_ip(w);                           // w = 1/d2 per lane, in place

        u64 wdx = f2mul(w, dx);
        u64 wdy = f2mul(w, dy);

        f2acc_add(sw, w);
        f2acc_add(Sx, wdx);
        f2acc_add(Sy, wdy);
        f2acc_fma(Sxx, wdx, dx);
        f2acc_fma(Sxy, wdx, dy);
        f2acc_fma(Syy, wdy, dy);
        f2acc_fma(Sqx, w, u1.x);
        f2acc_fma(Sqy, w, u1.y);
        f2acc_fma(Sdxqx, wdx, u1.x);
        f2acc_fma(Sdyqx, wdy, u1.x);
        f2acc_fma(Sdxqy, wdx, u1.y);
        f2acc_fma(Sdyqy, wdy, u1.y);
    }

    float* ob = out + (size_t)b * (2 * GSZ * GSZ);

    float swl, swh, sxl, sxh, syl, syh;
    float sxxl, sxxh, sxyl, sxyh, syyl, syyh;
    float sqxl, sqxh, sqyl, sqyh;
    float s1l, s1h, s2l, s2h, s3l, s3h, s4l, s4h;
    f2unpack(sw, swl, swh);    f2unpack(Sx, sxl, sxh);    f2unpack(Sy, syl, syh);
    f2unpack(Sxx, sxxl, sxxh); f2unpack(Sxy, sxyl, sxyh); f2unpack(Syy, syyl, syyh);
    f2unpack(Sqx, sqxl, sqxh); f2unpack(Sqy, sqyl, sqyh);
    f2unpack(Sdxqx, s1l, s1h); f2unpack(Sdyqx, s2l, s2h);
    f2unpack(Sdxqy, s3l, s3h); f2unpack(Sdyqy, s4l, s4h);

    mls_finish(swl, sxl, syl, sxxl, sxyl, syyl, sqxl, sqyl, s1l, s2l, s3l, s4l, ob, pixA);
    mls_finish(swh, sxh, syh, sxxh, sxyh, syyh, sqxh, sqyh, s1h, s2h, s3h, s4h, ob, pixA + 128);
}

extern "C" void kernel_launch(void* const* d_in, const int* in_sizes, int n_in,
                              void* d_out, int out_size)
{
    const float* sp = (const float*)d_in[0];   // (B, 68, 2)
    const float* dp = (const float*)d_in[1];   // (B, 68, 2)
    float* out = (float*)d_out;                // (B, 2, 32, 32)

    int B = in_sizes[0] / (NCTRL * 2);         // 512 for this problem
    dim3 grid(4, B);
    mls_warp_kernel<<<grid, 128>>>(sp, dp, out);
}